// round 4
// baseline (speedup 1.0000x reference)
#include <cuda_runtime.h>
#include <math.h>

#define NT    2048      // B*T = 64*32
#define CDIM  384
#define TDIM  32
#define NHEAD 6
#define HEADD 64
#define VOCABSZ 50257
#define NCB   786       // ceil(VOCAB/64) column blocks in logits GEMM

// ---- scratch (no allocations allowed) ----
__device__ float g_h[NT * CDIM];
__device__ float g_q[NT * CDIM];
__device__ float g_k[NT * CDIM];
__device__ float g_v[NT * CDIM];
__device__ float g_pmax[NT * NCB];
__device__ float g_psum[NT * NCB];
__device__ float g_rowloss[NT];

// ---------------------------------------------------------------------------
// Embedding: h = w_e[x] + pos_emb[t]
// ---------------------------------------------------------------------------
__global__ void embed_kernel(const int* __restrict__ x,
                             const float* __restrict__ w_e,
                             const float* __restrict__ pos) {
    int idx = blockIdx.x * blockDim.x + threadIdx.x;
    if (idx >= NT * CDIM) return;
    int bt = idx / CDIM, c = idx % CDIM;
    int tok = x[bt];
    g_h[idx] = w_e[(size_t)tok * CDIM + c] + pos[(bt % TDIM) * CDIM + c];
}

// ---------------------------------------------------------------------------
// GEMM: C[m][n] = sum_k A[m][k] * B[n][k] (+bias[n]).  Both operands K-major.
// 64x64 block tile, 256 threads, 4x4 per thread, K-chunks of 16.
// STATS: also emit per-(row, col-block) running-softmax partials (max, sumexp).
// ---------------------------------------------------------------------------
template <bool STATS>
__global__ void gemm_nt(const float* __restrict__ A, const float* __restrict__ B,
                        float* __restrict__ C, const float* __restrict__ bias,
                        int M, int N, int K) {
    __shared__ float Ash[16][64];
    __shared__ float Bsh[16][64];
    __shared__ float red[64][17];
    __shared__ float rowmax[64];

    const int tid = threadIdx.x;
    const int tx = tid & 15, ty = tid >> 4;
    const int bm = blockIdx.y * 64, bn = blockIdx.x * 64;

    const int lrow = tid >> 2;       // 0..63
    const int lk   = (tid & 3) * 4;  // 0,4,8,12

    float acc[4][4] = {};

    for (int k0 = 0; k0 < K; k0 += 16) {
        {   // A tile (M rows always in-range here)
            const float4 v = *(const float4*)&A[(size_t)(bm + lrow) * K + k0 + lk];
            Ash[lk + 0][lrow] = v.x; Ash[lk + 1][lrow] = v.y;
            Ash[lk + 2][lrow] = v.z; Ash[lk + 3][lrow] = v.w;
        }
        {   // B tile (guard N)
            int n = bn + lrow;
            float4 v = make_float4(0.f, 0.f, 0.f, 0.f);
            if (n < N) v = *(const float4*)&B[(size_t)n * K + k0 + lk];
            Bsh[lk + 0][lrow] = v.x; Bsh[lk + 1][lrow] = v.y;
            Bsh[lk + 2][lrow] = v.z; Bsh[lk + 3][lrow] = v.w;
        }
        __syncthreads();
#pragma unroll
        for (int kk = 0; kk < 16; kk++) {
            float4 a4 = *(const float4*)&Ash[kk][ty * 4];
            float4 b4 = *(const float4*)&Bsh[kk][tx * 4];
            float av[4] = {a4.x, a4.y, a4.z, a4.w};
            float bv[4] = {b4.x, b4.y, b4.z, b4.w};
#pragma unroll
            for (int i = 0; i < 4; i++)
#pragma unroll
                for (int j = 0; j < 4; j++)
                    acc[i][j] += av[i] * bv[j];
        }
        __syncthreads();
    }

    // epilogue: write C, optionally softmax partials
    float vals[4][4];
#pragma unroll
    for (int i = 0; i < 4; i++) {
        int m = bm + ty * 4 + i;
#pragma unroll
        for (int j = 0; j < 4; j++) {
            int n = bn + tx * 4 + j;
            if (n < N) {
                float v = acc[i][j] + (bias ? bias[n] : 0.f);
                C[(size_t)m * N + n] = v;
                vals[i][j] = v;
            } else {
                vals[i][j] = -INFINITY;
            }
        }
    }

    if (STATS) {
#pragma unroll
        for (int i = 0; i < 4; i++) {
            float mx = fmaxf(fmaxf(vals[i][0], vals[i][1]),
                             fmaxf(vals[i][2], vals[i][3]));
            red[ty * 4 + i][tx] = mx;
        }
        __syncthreads();
        if (tid < 64) {
            float mx = red[tid][0];
#pragma unroll
            for (int j = 1; j < 16; j++) mx = fmaxf(mx, red[tid][j]);
            rowmax[tid] = mx;
        }
        __syncthreads();
#pragma unroll
        for (int i = 0; i < 4; i++) {
            float mx = rowmax[ty * 4 + i];
            float s = 0.f;
#pragma unroll
            for (int j = 0; j < 4; j++) {
                float v = vals[i][j];
                s += (v == -INFINITY) ? 0.f : expf(v - mx);
            }
            red[ty * 4 + i][tx] = s;
        }
        __syncthreads();
        if (tid < 64) {
            float s = 0.f;
#pragma unroll
            for (int j = 0; j < 16; j++) s += red[tid][j];
            int m = bm + tid;
            g_pmax[(size_t)m * NCB + blockIdx.x] = rowmax[tid];
            g_psum[(size_t)m * NCB + blockIdx.x] = s;
        }
    }
}

// ---------------------------------------------------------------------------
// Attention for one (batch, head): T=32, D=64, causal softmax, h += attn
// ---------------------------------------------------------------------------
__global__ void attn_kernel() {
    __shared__ float qs[32][65];
    __shared__ float ks[32][65];
    __shared__ float vs[32][65];
    __shared__ float w[32][33];

    const int bh = blockIdx.x;            // b*NHEAD + head
    const int b = bh / NHEAD, hd = bh % NHEAD;
    const int tid = threadIdx.x;          // 256 threads
    const int base = (b * TDIM) * CDIM + hd * HEADD;

    for (int i = tid; i < 32 * 64; i += 256) {
        int t = i >> 6, d = i & 63;
        int g = base + t * CDIM + d;
        qs[t][d] = g_q[g];
        ks[t][d] = g_k[g];
        vs[t][d] = g_v[g];
    }
    __syncthreads();

    const float scale = 0.125f;  // 64^-0.5
    for (int i = tid; i < 32 * 32; i += 256) {
        int t = i >> 5, s = i & 31;
        float v = -INFINITY;
        if (s <= t) {
            float acc = 0.f;
#pragma unroll
            for (int d = 0; d < 64; d++) acc += qs[t][d] * ks[s][d];
            v = acc * scale;
        }
        w[t][s] = v;
    }
    __syncthreads();

    if (tid < 32) {
        int t = tid;
        float mx = -INFINITY;
        for (int s = 0; s <= t; s++) mx = fmaxf(mx, w[t][s]);
        float sum = 0.f;
        for (int s = 0; s <= t; s++) { float e = expf(w[t][s] - mx); w[t][s] = e; sum += e; }
        float inv = 1.f / sum;
        for (int s = 0; s <= t; s++) w[t][s] *= inv;
        for (int s = t + 1; s < 32; s++) w[t][s] = 0.f;
    }
    __syncthreads();

    for (int i = tid; i < 32 * 64; i += 256) {
        int t = i >> 6, d = i & 63;
        float acc = 0.f;
#pragma unroll
        for (int s = 0; s < 32; s++) acc += w[t][s] * vs[s][d];
        g_h[base + t * CDIM + d] += acc;   // unique (bt,c) per thread across grid
    }
}

// ---------------------------------------------------------------------------
// Loss: combine per-tile (max,sumexp) partials -> per-row loss
// ---------------------------------------------------------------------------
__global__ void loss_rows_kernel(const float* __restrict__ logits,
                                 const int* __restrict__ targets) {
    const int row = blockIdx.x;
    const int tid = threadIdx.x;  // 256
    float m = -INFINITY, s = 0.f;
    for (int cb = tid; cb < NCB; cb += 256) {
        float mi = g_pmax[(size_t)row * NCB + cb];
        float si = g_psum[(size_t)row * NCB + cb];
        if (mi > m) { s = s * expf(m - mi) + si; m = mi; }
        else if (mi > -INFINITY) { s += si * expf(mi - m); }
    }
    __shared__ float sm[256], ss[256];
    sm[tid] = m; ss[tid] = s;
    __syncthreads();
    for (int st = 128; st > 0; st >>= 1) {
        if (tid < st) {
            float m1 = sm[tid], s1 = ss[tid];
            float m2 = sm[tid + st], s2 = ss[tid + st];
            float M = fmaxf(m1, m2);
            float S = ((m1 > -INFINITY) ? s1 * expf(m1 - M) : 0.f) +
                      ((m2 > -INFINITY) ? s2 * expf(m2 - M) : 0.f);
            sm[tid] = M; ss[tid] = S;
        }
        __syncthreads();
    }
    if (tid == 0) {
        float logZ = sm[0] + logf(ss[0]);
        int t = targets[row];
        float lt = logits[(size_t)row * VOCABSZ + t];
        g_rowloss[row] = logZ - lt;
    }
}

__global__ void loss_final_kernel(float* __restrict__ out, int out_size) {
    __shared__ float sm[256];
    const int tid = threadIdx.x;
    float s = 0.f;
    for (int r = tid; r < NT; r += 256) s += g_rowloss[r];
    sm[tid] = s;
    __syncthreads();
    for (int st = 128; st > 0; st >>= 1) {
        if (tid < st) sm[tid] += sm[tid + st];
        __syncthreads();
    }
    if (tid == 0) {
        float loss = sm[0] / (float)NT;
        size_t logits_elems = (size_t)NT * VOCABSZ;
        if ((size_t)out_size > logits_elems) out[logits_elems] = loss;
    }
}

// ---------------------------------------------------------------------------
extern "C" void kernel_launch(void* const* d_in, const int* in_sizes, int n_in,
                              void* d_out, int out_size) {
    const int*   x       = (const int*)d_in[0];
    const int*   targets = (const int*)d_in[1];
    const float* w_e     = (const float*)d_in[2];
    const float* pos     = (const float*)d_in[3];
    const float* Wq      = (const float*)d_in[4];
    const float* Wk      = (const float*)d_in[5];
    const float* Wv      = (const float*)d_in[6];
    const float* lm_w    = (const float*)d_in[7];
    const float* lm_b    = (const float*)d_in[8];
    float* out = (float*)d_out;

    float *ph, *pq, *pk, *pv;
    cudaGetSymbolAddress((void**)&ph, g_h);
    cudaGetSymbolAddress((void**)&pq, g_q);
    cudaGetSymbolAddress((void**)&pk, g_k);
    cudaGetSymbolAddress((void**)&pv, g_v);

    embed_kernel<<<(NT * CDIM + 255) / 256, 256>>>(x, w_e, pos);

    dim3 qkvGrid(CDIM / 64, NT / 64);  // (6, 32)
    const size_t wstride = (size_t)NHEAD * HEADD * CDIM;  // per-layer weight
    for (int l = 0; l < 2; l++) {
        gemm_nt<false><<<qkvGrid, 256>>>(ph, Wq + l * wstride, pq, nullptr, NT, CDIM, CDIM);
        gemm_nt<false><<<qkvGrid, 256>>>(ph, Wk + l * wstride, pk, nullptr, NT, CDIM, CDIM);
        gemm_nt<false><<<qkvGrid, 256>>>(ph, Wv + l * wstride, pv, nullptr, NT, CDIM, CDIM);
        attn_kernel<<<(NT / TDIM) * NHEAD, 256>>>();  // 384 blocks
    }

    dim3 logitsGrid(NCB, NT / 64);  // (786, 32)
    gemm_nt<true><<<logitsGrid, 256>>>(ph, lm_w, out, lm_b, NT, VOCABSZ, CDIM);

    loss_rows_kernel<<<NT, 256>>>(out, targets);
    loss_final_kernel<<<1, 256>>>(out, out_size);
}

// round 6
// speedup vs baseline: 2.8206x; 2.8206x over previous
#include <cuda_runtime.h>
#include <math.h>
#include <stdint.h>

#define NT    2048      // B*T
#define CDIM  384
#define TDIM  32
#define NHEAD 6
#define HEADD 64
#define VOCABSZ 50257
#define TILE_M 128
#define TILE_N 128
#define NNB   393       // ceil(VOCAB/128) N-blocks
#define NCB   786       // stats blocks of 64 cols (2 per CTA N-tile)
#define KCH   32
#define NCHUNK 12       // 384/32

// ---- scratch ----
__device__ float g_h[NT * CDIM];
__device__ float g_q[NT * CDIM];
__device__ float g_k[NT * CDIM];
__device__ float g_v[NT * CDIM];
__device__ float g_pmax[NT * NCB];
__device__ float g_psum[NT * NCB];
__device__ float g_rowloss[NT];

// =========================================================================
// helpers
// =========================================================================
__device__ __forceinline__ uint32_t smem_u32(const void* p) {
    uint32_t a;
    asm("{ .reg .u64 t; cvta.to.shared.u64 t, %1; cvt.u32.u64 %0, t; }" : "=r"(a) : "l"(p));
    return a;
}
__device__ __forceinline__ float f2tf32f(float f) {
    uint32_t r;
    asm("cvt.rna.tf32.f32 %0, %1;" : "=r"(r) : "f"(f));
    return __uint_as_float(r);
}
__device__ __forceinline__ void mma_tf32(float c[4], const uint32_t a[4], const uint32_t b[2]) {
    asm volatile(
        "mma.sync.aligned.m16n8k8.row.col.f32.tf32.tf32.f32 "
        "{%0,%1,%2,%3}, {%4,%5,%6,%7}, {%8,%9}, {%0,%1,%2,%3};"
        : "+f"(c[0]), "+f"(c[1]), "+f"(c[2]), "+f"(c[3])
        : "r"(a[0]), "r"(a[1]), "r"(a[2]), "r"(a[3]), "r"(b[0]), "r"(b[1]));
}
#define LDS128(r, addr) \
    asm volatile("ld.shared.v4.b32 {%0,%1,%2,%3}, [%4];" \
        : "=r"((r)[0]), "=r"((r)[1]), "=r"((r)[2]), "=r"((r)[3]) : "r"(addr))
#define LDS64(r, addr) \
    asm volatile("ld.shared.v2.b32 {%0,%1}, [%2];" \
        : "=r"((r)[0]), "=r"((r)[1]) : "r"(addr))

// SMEM layout (bytes): bias[128] @0; buffers @1024:
//   A buf: 1024 + buf*16384       (16KB each, fragment-permuted)
//   B buf: 1024 + 32768 + buf*16384
// stage (epilogue, reuses buffers): @1024, 128x132 floats
#define SM_BUF    1024
#define SM_TOTAL  (1024 + 128 * 132 * 4)   // 68608

// ---- staging: global fp32 -> tf32 fragment-permuted SMEM ----
// A frag layout: float4 index = ((kc8*8 + mb)*32 + lane), reg in [0,4)
//   lane = (mi&7)*4 + (ki&3), reg = (mi>>3) + 2*(ki>>2);  mb=m>>4, kc8=k>>3
// B frag layout: float2 index = ((kc8*16 + nb)*32 + lane), reg in [0,2)
//   lane = (n&7)*4 + (ki&3), reg = ki>>2;  nb=n>>3
__device__ __forceinline__ void ldg_A(float4 v[4], const float* Ag, int tid) {
    const int rb = tid >> 3, j = tid & 7;
#pragma unroll
    for (int i = 0; i < 4; i++)
        v[i] = *(const float4*)(Ag + (size_t)(i * 32 + rb) * CDIM + j * 4);
}
__device__ __forceinline__ void ldg_B(float4 v[4], const float* Bg, int bn, int Ntot, int tid) {
    const int rb = tid >> 3, j = tid & 7;
#pragma unroll
    for (int i = 0; i < 4; i++) {
        int n = bn + i * 32 + rb;
        v[i] = (n < Ntot) ? *(const float4*)(Bg + (size_t)n * CDIM + j * 4)
                          : make_float4(0.f, 0.f, 0.f, 0.f);
    }
}
__device__ __forceinline__ void sts_A(float* dst, const float4 v[4], int tid) {
    const int rb = tid >> 3, j = tid & 7, kc8 = j >> 1;
#pragma unroll
    for (int i = 0; i < 4; i++) {
        int r = i * 32 + rb;
        int mb = r >> 4, mi = r & 15;
        int reg = (mi >> 3) + 2 * (j & 1);
        int base = ((kc8 * 8 + mb) * 32 + (mi & 7) * 4) * 4 + reg;
        dst[base]      = f2tf32f(v[i].x);
        dst[base + 4]  = f2tf32f(v[i].y);
        dst[base + 8]  = f2tf32f(v[i].z);
        dst[base + 12] = f2tf32f(v[i].w);
    }
}
__device__ __forceinline__ void sts_B(float* dst, const float4 v[4], int tid) {
    const int rb = tid >> 3, j = tid & 7, kc8 = j >> 1;
#pragma unroll
    for (int i = 0; i < 4; i++) {
        int r = i * 32 + rb;
        int nb = r >> 3, ni = r & 7;
        int base = ((kc8 * 16 + nb) * 32 + ni * 4) * 2 + (j & 1);
        dst[base]     = f2tf32f(v[i].x);
        dst[base + 2] = f2tf32f(v[i].y);
        dst[base + 4] = f2tf32f(v[i].z);
        dst[base + 6] = f2tf32f(v[i].w);
    }
}

__device__ __forceinline__ void compute_chunk(uint32_t Abuf, uint32_t Bbuf,
                                              int wm, int wn, int lid,
                                              float c[2][8][4]) {
#pragma unroll
    for (int ks = 0; ks < 4; ks++) {
        uint32_t a[2][4];
#pragma unroll
        for (int r = 0; r < 2; r++)
            LDS128(a[r], Abuf + ((ks * 8 + wm * 2 + r) * 32 + lid) * 16);
        uint32_t b[8][2];
#pragma unroll
        for (int nf = 0; nf < 8; nf++)
            LDS64(b[nf], Bbuf + ((ks * 16 + wn * 8 + nf) * 32 + lid) * 8);
#pragma unroll
        for (int r = 0; r < 2; r++)
#pragma unroll
            for (int nf = 0; nf < 8; nf++)
                mma_tf32(c[r][nf], a[r], b[nf]);
    }
}

__device__ __forceinline__ void supd(float& m, float& s, float v) {
    if (v > m) { s = s * __expf(m - v) + 1.f; m = v; }
    else       { s += __expf(v - m); }
}

// =========================================================================
// tf32 tensor GEMM:  C[m][n] = sum_k A[m][k]*B[n][k] (+bias), K=384
// grid: (16, Nblocks, nz); blockIdx.z selects B/C pair (fused QKV)
// =========================================================================
template <bool STATS>
__global__ __launch_bounds__(256)
void mma_gemm(const float* __restrict__ A,
              const float* __restrict__ B0, const float* __restrict__ B1,
              const float* __restrict__ B2,
              float* __restrict__ C0, float* __restrict__ C1, float* __restrict__ C2,
              const float* __restrict__ bias, int Ntot) {
    extern __shared__ __align__(1024) char smem[];
    const int tid = threadIdx.x;
    const int lid = tid & 31, wid = tid >> 5;
    const int wm = wid >> 1, wn = wid & 1;
    const int bm = blockIdx.x * TILE_M;
    const int bn = blockIdx.y * TILE_N;
    const float* B = (blockIdx.z == 0) ? B0 : (blockIdx.z == 1 ? B1 : B2);
    float* C = (blockIdx.z == 0) ? C0 : (blockIdx.z == 1 ? C1 : C2);

    float* biasS = (float*)smem;
    float* stage = (float*)(smem + SM_BUF);
    const uint32_t sb = smem_u32(smem);

    if (tid < TILE_N) {
        int n = bn + tid;
        biasS[tid] = (bias != nullptr && n < Ntot) ? bias[n] : 0.f;
    }

    float c[2][8][4];
#pragma unroll
    for (int r = 0; r < 2; r++)
#pragma unroll
        for (int nf = 0; nf < 8; nf++)
#pragma unroll
            for (int e = 0; e < 4; e++) c[r][nf][e] = 0.f;

    // prologue: stage chunk 0 into buf 0
    {
        float4 va[4], vb[4];
        ldg_A(va, A + (size_t)bm * CDIM, tid);
        ldg_B(vb, B, bn, Ntot, tid);
        sts_A((float*)(smem + SM_BUF), va, tid);
        sts_B((float*)(smem + SM_BUF + 32768), vb, tid);
    }
    __syncthreads();

    for (int kc = 0; kc < NCHUNK; kc++) {
        const int buf = kc & 1;
        float4 va[4], vb[4];
        if (kc + 1 < NCHUNK) {   // prefetch next chunk (hide behind compute)
            ldg_A(va, A + (size_t)bm * CDIM + (kc + 1) * KCH, tid);
            ldg_B(vb, B + (kc + 1) * KCH, bn, Ntot, tid);
        }
        compute_chunk(sb + SM_BUF + buf * 16384,
                      sb + SM_BUF + 32768 + buf * 16384, wm, wn, lid, c);
        __syncthreads();
        if (kc + 1 < NCHUNK) {
            sts_A((float*)(smem + SM_BUF + (buf ^ 1) * 16384), va, tid);
            sts_B((float*)(smem + SM_BUF + 32768 + (buf ^ 1) * 16384), vb, tid);
            __syncthreads();
        }
    }

    // ---- epilogue: bias, stats, staged coalesced store ----
    float rm[2][2], rs[2][2];
#pragma unroll
    for (int r = 0; r < 2; r++)
#pragma unroll
        for (int h = 0; h < 2; h++) { rm[r][h] = -INFINITY; rs[r][h] = 0.f; }

    const int g = lid >> 2, t4 = lid & 3;
#pragma unroll
    for (int r = 0; r < 2; r++) {
        const int row = wm * 32 + r * 16 + g;
#pragma unroll
        for (int nf = 0; nf < 8; nf++) {
            const int col = wn * 64 + nf * 8 + t4 * 2;
            const float b0 = biasS[col], b1 = biasS[col + 1];
            float v0 = c[r][nf][0] + b0, v1 = c[r][nf][1] + b1;
            float v2 = c[r][nf][2] + b0, v3 = c[r][nf][3] + b1;
            *(float2*)&stage[row * 132 + col]       = make_float2(v0, v1);
            *(float2*)&stage[(row + 8) * 132 + col] = make_float2(v2, v3);
            if (STATS) {
                int n = bn + col;
                if (n < Ntot)     { supd(rm[r][0], rs[r][0], v0); supd(rm[r][1], rs[r][1], v2); }
                if (n + 1 < Ntot) { supd(rm[r][0], rs[r][0], v1); supd(rm[r][1], rs[r][1], v3); }
            }
        }
    }

    if (STATS) {
#pragma unroll
        for (int r = 0; r < 2; r++)
#pragma unroll
            for (int h = 0; h < 2; h++) {
                float m = rm[r][h], s = rs[r][h];
#pragma unroll
                for (int off = 1; off <= 2; off <<= 1) {
                    float om = __shfl_xor_sync(0xffffffffu, m, off);
                    float os = __shfl_xor_sync(0xffffffffu, s, off);
                    float M = fmaxf(m, om);
                    float S = ((m > -INFINITY) ? s * __expf(m - M) : 0.f) +
                              ((om > -INFINITY) ? os * __expf(om - M) : 0.f);
                    m = M; s = S;
                }
                if (t4 == 0) {
                    int mrow = bm + wm * 32 + r * 16 + h * 8 + g;
                    size_t idx = (size_t)mrow * NCB + blockIdx.y * 2 + wn;
                    g_pmax[idx] = m;
                    g_psum[idx] = s;
                }
            }
    }

    __syncthreads();
#pragma unroll 8
    for (int it = 0; it < 64; it++) {
        int idx = it * 256 + tid;
        int rr = idx >> 7, cc = idx & 127;
        int n = bn + cc;
        if (n < Ntot) C[(size_t)(bm + rr) * Ntot + n] = stage[rr * 132 + cc];
    }
}

// =========================================================================
// Embedding
// =========================================================================
__global__ void embed_kernel(const int* __restrict__ x,
                             const float* __restrict__ w_e,
                             const float* __restrict__ pos) {
    int idx = blockIdx.x * blockDim.x + threadIdx.x;
    if (idx >= NT * CDIM) return;
    int bt = idx / CDIM, c = idx % CDIM;
    int tok = x[bt];
    g_h[idx] = w_e[(size_t)tok * CDIM + c] + pos[(bt % TDIM) * CDIM + c];
}

// =========================================================================
// Attention (T=32, D=64, causal, h += attn)
// =========================================================================
__global__ void attn_kernel() {
    __shared__ float qs[32][65];
    __shared__ float ks[32][65];
    __shared__ float vs[32][65];
    __shared__ float w[32][33];

    const int bh = blockIdx.x;
    const int b = bh / NHEAD, hd = bh % NHEAD;
    const int tid = threadIdx.x;
    const int base = (b * TDIM) * CDIM + hd * HEADD;

    for (int i = tid; i < 32 * 64; i += 256) {
        int t = i >> 6, d = i & 63;
        int g = base + t * CDIM + d;
        qs[t][d] = g_q[g];
        ks[t][d] = g_k[g];
        vs[t][d] = g_v[g];
    }
    __syncthreads();

    const float scale = 0.125f;
    for (int i = tid; i < 32 * 32; i += 256) {
        int t = i >> 5, s = i & 31;
        float v = -INFINITY;
        if (s <= t) {
            float acc = 0.f;
#pragma unroll
            for (int d = 0; d < 64; d++) acc += qs[t][d] * ks[s][d];
            v = acc * scale;
        }
        w[t][s] = v;
    }
    __syncthreads();

    if (tid < 32) {
        int t = tid;
        float mx = -INFINITY;
        for (int s = 0; s <= t; s++) mx = fmaxf(mx, w[t][s]);
        float sum = 0.f;
        for (int s = 0; s <= t; s++) { float e = expf(w[t][s] - mx); w[t][s] = e; sum += e; }
        float inv = 1.f / sum;
        for (int s = 0; s <= t; s++) w[t][s] *= inv;
        for (int s = t + 1; s < 32; s++) w[t][s] = 0.f;
    }
    __syncthreads();

    for (int i = tid; i < 32 * 64; i += 256) {
        int t = i >> 6, d = i & 63;
        float acc = 0.f;
#pragma unroll
        for (int s = 0; s < 32; s++) acc += w[t][s] * vs[s][d];
        g_h[base + t * CDIM + d] += acc;
    }
}

// =========================================================================
// Loss
// =========================================================================
__global__ void loss_rows_kernel(const float* __restrict__ logits,
                                 const int* __restrict__ targets) {
    const int row = blockIdx.x;
    const int tid = threadIdx.x;
    float m = -INFINITY, s = 0.f;
    for (int cb = tid; cb < NCB; cb += 256) {
        float mi = g_pmax[(size_t)row * NCB + cb];
        float si = g_psum[(size_t)row * NCB + cb];
        if (mi > m) { s = s * expf(m - mi) + si; m = mi; }
        else if (mi > -INFINITY) { s += si * expf(mi - m); }
    }
    __shared__ float sm[256], ss[256];
    sm[tid] = m; ss[tid] = s;
    __syncthreads();
    for (int st = 128; st > 0; st >>= 1) {
        if (tid < st) {
            float m1 = sm[tid], s1 = ss[tid];
            float m2 = sm[tid + st], s2 = ss[tid + st];
            float M = fmaxf(m1, m2);
            float S = ((m1 > -INFINITY) ? s1 * expf(m1 - M) : 0.f) +
                      ((m2 > -INFINITY) ? s2 * expf(m2 - M) : 0.f);
            sm[tid] = M; ss[tid] = S;
        }
        __syncthreads();
    }
    if (tid == 0) {
        float logZ = sm[0] + logf(ss[0]);
        int t = targets[row];
        float lt = logits[(size_t)row * VOCABSZ + t];
        g_rowloss[row] = logZ - lt;
    }
}

__global__ void loss_final_kernel(float* __restrict__ out, int out_size) {
    __shared__ float sm[256];
    const int tid = threadIdx.x;
    float s = 0.f;
    for (int r = tid; r < NT; r += 256) s += g_rowloss[r];
    sm[tid] = s;
    __syncthreads();
    for (int st = 128; st > 0; st >>= 1) {
        if (tid < st) sm[tid] += sm[tid + st];
        __syncthreads();
    }
    if (tid == 0) {
        float loss = sm[0] / (float)NT;
        size_t logits_elems = (size_t)NT * VOCABSZ;
        if ((size_t)out_size > logits_elems) out[logits_elems] = loss;
    }
}

// =========================================================================
extern "C" void kernel_launch(void* const* d_in, const int* in_sizes, int n_in,
                              void* d_out, int out_size) {
    const int*   x       = (const int*)d_in[0];
    const int*   targets = (const int*)d_in[1];
    const float* w_e     = (const float*)d_in[2];
    const float* pos     = (const float*)d_in[3];
    const float* Wq      = (const float*)d_in[4];
    const float* Wk      = (const float*)d_in[5];
    const float* Wv      = (const float*)d_in[6];
    const float* lm_w    = (const float*)d_in[7];
    const float* lm_b    = (const float*)d_in[8];
    float* out = (float*)d_out;

    float *ph, *pq, *pk, *pv;
    cudaGetSymbolAddress((void**)&ph, g_h);
    cudaGetSymbolAddress((void**)&pq, g_q);
    cudaGetSymbolAddress((void**)&pk, g_k);
    cudaGetSymbolAddress((void**)&pv, g_v);

    cudaFuncSetAttribute(mma_gemm<false>, cudaFuncAttributeMaxDynamicSharedMemorySize, SM_TOTAL);
    cudaFuncSetAttribute(mma_gemm<true>,  cudaFuncAttributeMaxDynamicSharedMemorySize, SM_TOTAL);

    embed_kernel<<<(NT * CDIM + 255) / 256, 256>>>(x, w_e, pos);

    const size_t wstride = (size_t)NHEAD * HEADD * CDIM;
    for (int l = 0; l < 2; l++) {
        mma_gemm<false><<<dim3(NT / TILE_M, CDIM / TILE_N, 3), 256, SM_TOTAL>>>(
            ph, Wq + l * wstride, Wk + l * wstride, Wv + l * wstride,
            pq, pk, pv, nullptr, CDIM);
        attn_kernel<<<(NT / TDIM) * NHEAD, 256>>>();
    }

    mma_gemm<true><<<dim3(NT / TILE_M, NNB, 1), 256, SM_TOTAL>>>(
        ph, lm_w, lm_w, lm_w, out, out, out, lm_b, VOCABSZ);

    loss_rows_kernel<<<NT, 256>>>(out, targets);
    loss_final_kernel<<<1, 256>>>(out, out_size);
}

// round 7
// speedup vs baseline: 4.6500x; 1.6486x over previous
#include <cuda_runtime.h>
#include <math.h>
#include <stdint.h>

#define NT    2048      // B*T
#define CDIM  384
#define TDIM  32
#define NHEAD 6
#define HEADD 64
#define VOCABSZ 50257
#define TILE_M 128
#define TILE_N 128
#define NMB   16        // NT/128
#define NNB   393       // ceil(VOCAB/128)
#define NCB   786       // stats blocks of 64 cols (2 per CTA N-tile)
#define KCH   32
#define NCHUNK 12       // 384/32
#define CHUNK_F 4096    // floats per permuted chunk (128 x 32)
#define NSTAGE 3
#define STAGE_BYTES 32768
#define QKV_MAT_F (3 * NCHUNK * CHUNK_F)   // floats per permuted qkv matrix

// ---- scratch ----
__device__ float g_h[NT * CDIM];
__device__ float g_q[NT * CDIM];
__device__ float g_k[NT * CDIM];
__device__ float g_v[NT * CDIM];
__device__ float g_pmax[NT * NCB];
__device__ float g_psum[NT * NCB];
__device__ float g_rowloss[NT];
__device__ float g_aperm[NMB * NCHUNK * CHUNK_F];            // 3 MB
__device__ float g_blm[NNB * NCHUNK * CHUNK_F];              // 77 MB
__device__ float g_bqkv[2 * 3 * QKV_MAT_F];                  // 3.5 MB

// =========================================================================
// helpers
// =========================================================================
__device__ __forceinline__ uint32_t smem_u32(const void* p) {
    uint32_t a;
    asm("{ .reg .u64 t; cvta.to.shared.u64 t, %1; cvt.u32.u64 %0, t; }" : "=r"(a) : "l"(p));
    return a;
}
__device__ __forceinline__ float f2tf32f(float f) {
    uint32_t r;
    asm("cvt.rna.tf32.f32 %0, %1;" : "=r"(r) : "f"(f));
    return __uint_as_float(r);
}
__device__ __forceinline__ void mma_tf32(float c[4], const uint32_t a[4], const uint32_t b[2]) {
    asm volatile(
        "mma.sync.aligned.m16n8k8.row.col.f32.tf32.tf32.f32 "
        "{%0,%1,%2,%3}, {%4,%5,%6,%7}, {%8,%9}, {%0,%1,%2,%3};"
        : "+f"(c[0]), "+f"(c[1]), "+f"(c[2]), "+f"(c[3])
        : "r"(a[0]), "r"(a[1]), "r"(a[2]), "r"(a[3]), "r"(b[0]), "r"(b[1]));
}
#define LDS128(r, addr) \
    asm volatile("ld.shared.v4.b32 {%0,%1,%2,%3}, [%4];" \
        : "=r"((r)[0]), "=r"((r)[1]), "=r"((r)[2]), "=r"((r)[3]) : "r"(addr))
#define LDS64(r, addr) \
    asm volatile("ld.shared.v2.b32 {%0,%1}, [%2];" \
        : "=r"((r)[0]), "=r"((r)[1]) : "r"(addr))
#define CP_ASYNC16(dst, src) \
    asm volatile("cp.async.cg.shared.global [%0], [%1], 16;" :: "r"(dst), "l"(src) : "memory")
#define CP_COMMIT() asm volatile("cp.async.commit_group;" ::: "memory")
#define CP_WAIT1()  asm volatile("cp.async.wait_group 1;" ::: "memory")

// SMEM: bias[128] @0 ; 3 stages of (A 16KB + B 16KB) @1024 ; epilogue stage reuses
#define SM_STAGE0 1024
#define SM_TOTAL  (1024 + NSTAGE * STAGE_BYTES)   // 99328

// Fragment-permuted layouts (within a 128x32 chunk):
//  A elem (m,k): frag=(k>>3)*8+(m>>4); lane=(m&7)*4+(k&3); reg=((m>>3)&1)+2*((k>>2)&1)
//    float index = frag*128 + lane*4 + reg
//  B elem (n,k): frag=(k>>3)*16+(n>>3); lane=(n&7)*4+(k&3); reg=(k>>2)&1
//    float index = frag*64 + lane*2 + reg

__device__ __forceinline__ void compute_chunk(uint32_t Abuf, uint32_t Bbuf,
                                              int wm, int wn, int lid,
                                              float c[2][8][4]) {
#pragma unroll
    for (int ks = 0; ks < 4; ks++) {
        uint32_t a[2][4];
#pragma unroll
        for (int r = 0; r < 2; r++)
            LDS128(a[r], Abuf + ((ks * 8 + wm * 2 + r) * 32 + lid) * 16);
        uint32_t b[8][2];
#pragma unroll
        for (int nf = 0; nf < 8; nf++)
            LDS64(b[nf], Bbuf + ((ks * 16 + wn * 8 + nf) * 32 + lid) * 8);
#pragma unroll
        for (int r = 0; r < 2; r++)
#pragma unroll
            for (int nf = 0; nf < 8; nf++)
                mma_tf32(c[r][nf], a[r], b[nf]);
    }
}

__device__ __forceinline__ void supd(float& m, float& s, float v) {
    if (v > m) { s = s * __expf(m - v) + 1.f; m = v; }
    else       { s += __expf(v - m); }
}

// =========================================================================
// Permutation kernels (global fp32 -> tf32 fragment-permuted global)
// =========================================================================
__global__ void aperm_kernel(const float* __restrict__ A) {
    __shared__ float sbuf[CHUNK_F];
    const int tid = threadIdx.x;
    const int mb = blockIdx.x, kc = blockIdx.y;
    const int rb = tid >> 3, j = tid & 7, kc8 = j >> 1;
    const float* Ag = A + (size_t)(mb * 128) * CDIM + kc * KCH;
#pragma unroll
    for (int i = 0; i < 4; i++) {
        int r = i * 32 + rb;
        float4 v = *(const float4*)(Ag + (size_t)r * CDIM + j * 4);
        int mbl = r >> 4, mi = r & 15;
        int reg = (mi >> 3) + 2 * (j & 1);
        int base = ((kc8 * 8 + mbl) * 32 + (mi & 7) * 4) * 4 + reg;
        sbuf[base]      = f2tf32f(v.x);
        sbuf[base + 4]  = f2tf32f(v.y);
        sbuf[base + 8]  = f2tf32f(v.z);
        sbuf[base + 12] = f2tf32f(v.w);
    }
    __syncthreads();
    float* out = g_aperm + ((size_t)mb * NCHUNK + kc) * CHUNK_F;
#pragma unroll
    for (int i = 0; i < 4; i++)
        *(float4*)(out + i * 1024 + tid * 4) = *(const float4*)&sbuf[i * 1024 + tid * 4];
}

__global__ void bperm_kernel(const float* __restrict__ B0, const float* __restrict__ B1,
                             const float* __restrict__ B2,
                             float* __restrict__ O0, float* __restrict__ O1,
                             float* __restrict__ O2, int Ntot) {
    __shared__ float sbuf[CHUNK_F];
    const int tid = threadIdx.x;
    const int nb = blockIdx.x, kc = blockIdx.y, z = blockIdx.z;
    const float* B = (z == 0) ? B0 : (z == 1 ? B1 : B2);
    float* O = (z == 0) ? O0 : (z == 1 ? O1 : O2);
    const int rb = tid >> 3, j = tid & 7, kc8 = j >> 1;
#pragma unroll
    for (int i = 0; i < 4; i++) {
        int r = i * 32 + rb;
        int n = nb * 128 + r;
        float4 v = (n < Ntot) ? *(const float4*)(B + (size_t)n * CDIM + kc * KCH + j * 4)
                              : make_float4(0.f, 0.f, 0.f, 0.f);
        int nbl = r >> 3, ni = r & 7;
        int base = ((kc8 * 16 + nbl) * 32 + ni * 4) * 2 + (j & 1);
        sbuf[base]     = f2tf32f(v.x);
        sbuf[base + 2] = f2tf32f(v.y);
        sbuf[base + 4] = f2tf32f(v.z);
        sbuf[base + 6] = f2tf32f(v.w);
    }
    __syncthreads();
    float* out = O + ((size_t)nb * NCHUNK + kc) * CHUNK_F;
#pragma unroll
    for (int i = 0; i < 4; i++)
        *(float4*)(out + i * 1024 + tid * 4) = *(const float4*)&sbuf[i * 1024 + tid * 4];
}

// =========================================================================
// tf32 tensor GEMM over pre-permuted operands.
// grid: (NMB, Nblocks, nz); z selects B/C pair (fused QKV). A = g_aperm.
// =========================================================================
template <bool STATS>
__global__ __launch_bounds__(256)
void mma_gemm(const float* __restrict__ Bp0, const float* __restrict__ Bp1,
              const float* __restrict__ Bp2,
              float* __restrict__ C0, float* __restrict__ C1, float* __restrict__ C2,
              const float* __restrict__ bias, int Ntot) {
    extern __shared__ __align__(1024) char smem[];
    const int tid = threadIdx.x;
    const int lid = tid & 31, wid = tid >> 5;
    const int wm = wid >> 1, wn = wid & 1;
    const int bm = blockIdx.x * TILE_M;
    const int bn = blockIdx.y * TILE_N;
    const float* Bperm = (blockIdx.z == 0) ? Bp0 : (blockIdx.z == 1 ? Bp1 : Bp2);
    float* C = (blockIdx.z == 0) ? C0 : (blockIdx.z == 1 ? C1 : C2);

    const float* Ac = g_aperm + (size_t)blockIdx.x * NCHUNK * CHUNK_F;
    const float* Bc = Bperm + (size_t)blockIdx.y * NCHUNK * CHUNK_F;

    float* biasS = (float*)smem;
    float* stage = (float*)(smem + SM_STAGE0);
    const uint32_t sb = smem_u32(smem);

    if (tid < TILE_N) {
        int n = bn + tid;
        biasS[tid] = (bias != nullptr && n < Ntot) ? bias[n] : 0.f;
    }

    float c[2][8][4];
#pragma unroll
    for (int r = 0; r < 2; r++)
#pragma unroll
        for (int nf = 0; nf < 8; nf++)
#pragma unroll
            for (int e = 0; e < 4; e++) c[r][nf][e] = 0.f;

    // ---- cp.async copy of one chunk into stage s ----
    auto issue = [&](int kcc, int s) {
        uint32_t dA = sb + SM_STAGE0 + s * STAGE_BYTES + tid * 16;
        uint32_t dB = dA + 16384;
        const float* srcA = Ac + (size_t)kcc * CHUNK_F + tid * 4;
        const float* srcB = Bc + (size_t)kcc * CHUNK_F + tid * 4;
#pragma unroll
        for (int i = 0; i < 4; i++) {
            CP_ASYNC16(dA + i * 4096, srcA + i * 1024);
            CP_ASYNC16(dB + i * 4096, srcB + i * 1024);
        }
    };

    issue(0, 0); CP_COMMIT();
    issue(1, 1); CP_COMMIT();

    for (int kc = 0; kc < NCHUNK; kc++) {
        CP_WAIT1();
        __syncthreads();                 // chunk kc visible to all; buf (kc-1)%3 free
        if (kc + 2 < NCHUNK) issue(kc + 2, (kc + 2) % NSTAGE);
        CP_COMMIT();
        const uint32_t base = sb + SM_STAGE0 + (kc % NSTAGE) * STAGE_BYTES;
        compute_chunk(base, base + 16384, wm, wn, lid, c);
    }
    __syncthreads();                     // all compute done before stage reuse

    // ---- epilogue: bias, stats, staged coalesced store ----
    float rm[2][2], rs[2][2];
#pragma unroll
    for (int r = 0; r < 2; r++)
#pragma unroll
        for (int h = 0; h < 2; h++) { rm[r][h] = -INFINITY; rs[r][h] = 0.f; }

    const int g = lid >> 2, t4 = lid & 3;
#pragma unroll
    for (int r = 0; r < 2; r++) {
        const int row = wm * 32 + r * 16 + g;
#pragma unroll
        for (int nf = 0; nf < 8; nf++) {
            const int col = wn * 64 + nf * 8 + t4 * 2;
            const float b0 = biasS[col], b1 = biasS[col + 1];
            float v0 = c[r][nf][0] + b0, v1 = c[r][nf][1] + b1;
            float v2 = c[r][nf][2] + b0, v3 = c[r][nf][3] + b1;
            *(float2*)&stage[row * 132 + col]       = make_float2(v0, v1);
            *(float2*)&stage[(row + 8) * 132 + col] = make_float2(v2, v3);
            if (STATS) {
                int n = bn + col;
                if (n < Ntot)     { supd(rm[r][0], rs[r][0], v0); supd(rm[r][1], rs[r][1], v2); }
                if (n + 1 < Ntot) { supd(rm[r][0], rs[r][0], v1); supd(rm[r][1], rs[r][1], v3); }
            }
        }
    }

    if (STATS) {
#pragma unroll
        for (int r = 0; r < 2; r++)
#pragma unroll
            for (int h = 0; h < 2; h++) {
                float m = rm[r][h], s = rs[r][h];
#pragma unroll
                for (int off = 1; off <= 2; off <<= 1) {
                    float om = __shfl_xor_sync(0xffffffffu, m, off);
                    float os = __shfl_xor_sync(0xffffffffu, s, off);
                    float M = fmaxf(m, om);
                    float S = ((m > -INFINITY) ? s * __expf(m - M) : 0.f) +
                              ((om > -INFINITY) ? os * __expf(om - M) : 0.f);
                    m = M; s = S;
                }
                if (t4 == 0) {
                    int mrow = bm + wm * 32 + r * 16 + h * 8 + g;
                    size_t idx = (size_t)mrow * NCB + blockIdx.y * 2 + wn;
                    g_pmax[idx] = m;
                    g_psum[idx] = s;
                }
            }
    }

    __syncthreads();
#pragma unroll 8
    for (int it = 0; it < 64; it++) {
        int idx = it * 256 + tid;
        int rr = idx >> 7, cc = idx & 127;
        int n = bn + cc;
        if (n < Ntot) C[(size_t)(bm + rr) * Ntot + n] = stage[rr * 132 + cc];
    }
}

// =========================================================================
// Embedding
// =========================================================================
__global__ void embed_kernel(const int* __restrict__ x,
                             const float* __restrict__ w_e,
                             const float* __restrict__ pos) {
    int idx = blockIdx.x * blockDim.x + threadIdx.x;
    if (idx >= NT * CDIM) return;
    int bt = idx / CDIM, c = idx % CDIM;
    int tok = x[bt];
    g_h[idx] = w_e[(size_t)tok * CDIM + c] + pos[(bt % TDIM) * CDIM + c];
}

// =========================================================================
// Attention (T=32, D=64, causal, h += attn)
// =========================================================================
__global__ void attn_kernel() {
    __shared__ float qs[32][65];
    __shared__ float ks[32][65];
    __shared__ float vs[32][65];
    __shared__ float w[32][33];

    const int bh = blockIdx.x;
    const int b = bh / NHEAD, hd = bh % NHEAD;
    const int tid = threadIdx.x;
    const int base = (b * TDIM) * CDIM + hd * HEADD;

    for (int i = tid; i < 32 * 64; i += 256) {
        int t = i >> 6, d = i & 63;
        int g = base + t * CDIM + d;
        qs[t][d] = g_q[g];
        ks[t][d] = g_k[g];
        vs[t][d] = g_v[g];
    }
    __syncthreads();

    const float scale = 0.125f;
    for (int i = tid; i < 32 * 32; i += 256) {
        int t = i >> 5, s = i & 31;
        float v = -INFINITY;
        if (s <= t) {
            float acc = 0.f;
#pragma unroll
            for (int d = 0; d < 64; d++) acc += qs[t][d] * ks[s][d];
            v = acc * scale;
        }
        w[t][s] = v;
    }
    __syncthreads();

    if (tid < 32) {
        int t = tid;
        float mx = -INFINITY;
        for (int s = 0; s <= t; s++) mx = fmaxf(mx, w[t][s]);
        float sum = 0.f;
        for (int s = 0; s <= t; s++) { float e = expf(w[t][s] - mx); w[t][s] = e; sum += e; }
        float inv = 1.f / sum;
        for (int s = 0; s <= t; s++) w[t][s] *= inv;
        for (int s = t + 1; s < 32; s++) w[t][s] = 0.f;
    }
    __syncthreads();

    for (int i = tid; i < 32 * 64; i += 256) {
        int t = i >> 6, d = i & 63;
        float acc = 0.f;
#pragma unroll
        for (int s = 0; s < 32; s++) acc += w[t][s] * vs[s][d];
        g_h[base + t * CDIM + d] += acc;
    }
}

// =========================================================================
// Loss
// =========================================================================
__global__ void loss_rows_kernel(const float* __restrict__ logits,
                                 const int* __restrict__ targets) {
    const int row = blockIdx.x;
    const int tid = threadIdx.x;
    float m = -INFINITY, s = 0.f;
    for (int cb = tid; cb < NCB; cb += 256) {
        float mi = g_pmax[(size_t)row * NCB + cb];
        float si = g_psum[(size_t)row * NCB + cb];
        if (mi > m) { s = s * expf(m - mi) + si; m = mi; }
        else if (mi > -INFINITY) { s += si * expf(mi - m); }
    }
    __shared__ float sm[256], ss[256];
    sm[tid] = m; ss[tid] = s;
    __syncthreads();
    for (int st = 128; st > 0; st >>= 1) {
        if (tid < st) {
            float m1 = sm[tid], s1 = ss[tid];
            float m2 = sm[tid + st], s2 = ss[tid + st];
            float M = fmaxf(m1, m2);
            float S = ((m1 > -INFINITY) ? s1 * expf(m1 - M) : 0.f) +
                      ((m2 > -INFINITY) ? s2 * expf(m2 - M) : 0.f);
            sm[tid] = M; ss[tid] = S;
        }
        __syncthreads();
    }
    if (tid == 0) {
        float logZ = sm[0] + logf(ss[0]);
        int t = targets[row];
        float lt = logits[(size_t)row * VOCABSZ + t];
        g_rowloss[row] = logZ - lt;
    }
}

__global__ void loss_final_kernel(float* __restrict__ out, int out_size) {
    __shared__ float sm[256];
    const int tid = threadIdx.x;
    float s = 0.f;
    for (int r = tid; r < NT; r += 256) s += g_rowloss[r];
    sm[tid] = s;
    __syncthreads();
    for (int st = 128; st > 0; st >>= 1) {
        if (tid < st) sm[tid] += sm[tid + st];
        __syncthreads();
    }
    if (tid == 0) {
        float loss = sm[0] / (float)NT;
        size_t logits_elems = (size_t)NT * VOCABSZ;
        if ((size_t)out_size > logits_elems) out[logits_elems] = loss;
    }
}

// =========================================================================
extern "C" void kernel_launch(void* const* d_in, const int* in_sizes, int n_in,
                              void* d_out, int out_size) {
    const int*   x       = (const int*)d_in[0];
    const int*   targets = (const int*)d_in[1];
    const float* w_e     = (const float*)d_in[2];
    const float* pos     = (const float*)d_in[3];
    const float* Wq      = (const float*)d_in[4];
    const float* Wk      = (const float*)d_in[5];
    const float* Wv      = (const float*)d_in[6];
    const float* lm_w    = (const float*)d_in[7];
    const float* lm_b    = (const float*)d_in[8];
    float* out = (float*)d_out;

    float *ph, *pq, *pk, *pv, *pblm, *pbqkv;
    cudaGetSymbolAddress((void**)&ph, g_h);
    cudaGetSymbolAddress((void**)&pq, g_q);
    cudaGetSymbolAddress((void**)&pk, g_k);
    cudaGetSymbolAddress((void**)&pv, g_v);
    cudaGetSymbolAddress((void**)&pblm, g_blm);
    cudaGetSymbolAddress((void**)&pbqkv, g_bqkv);

    cudaFuncSetAttribute(mma_gemm<false>, cudaFuncAttributeMaxDynamicSharedMemorySize, SM_TOTAL);
    cudaFuncSetAttribute(mma_gemm<true>,  cudaFuncAttributeMaxDynamicSharedMemorySize, SM_TOTAL);

    embed_kernel<<<(NT * CDIM + 255) / 256, 256>>>(x, w_e, pos);

    const size_t wstride = (size_t)NHEAD * HEADD * CDIM;
    // permute all weights (lm_w + 2 layers of Q/K/V)
    bperm_kernel<<<dim3(NNB, NCHUNK, 1), 256>>>(lm_w, lm_w, lm_w, pblm, pblm, pblm, VOCABSZ);
    for (int l = 0; l < 2; l++) {
        float* bq = pbqkv + (size_t)(l * 3 + 0) * QKV_MAT_F;
        float* bk = pbqkv + (size_t)(l * 3 + 1) * QKV_MAT_F;
        float* bv = pbqkv + (size_t)(l * 3 + 2) * QKV_MAT_F;
        bperm_kernel<<<dim3(3, NCHUNK, 3), 256>>>(
            Wq + l * wstride, Wk + l * wstride, Wv + l * wstride, bq, bk, bv, CDIM);
    }

    for (int l = 0; l < 2; l++) {
        float* bq = pbqkv + (size_t)(l * 3 + 0) * QKV_MAT_F;
        float* bk = pbqkv + (size_t)(l * 3 + 1) * QKV_MAT_F;
        float* bv = pbqkv + (size_t)(l * 3 + 2) * QKV_MAT_F;
        aperm_kernel<<<dim3(NMB, NCHUNK), 256>>>(ph);
        mma_gemm<false><<<dim3(NMB, 3, 3), 256, SM_TOTAL>>>(
            bq, bk, bv, pq, pk, pv, nullptr, CDIM);
        attn_kernel<<<(NT / TDIM) * NHEAD, 256>>>();
    }

    aperm_kernel<<<dim3(NMB, NCHUNK), 256>>>(ph);
    mma_gemm<true><<<dim3(NMB, NNB, 1), 256, SM_TOTAL>>>(
        pblm, pblm, pblm, out, out, out, lm_b, VOCABSZ);

    loss_rows_kernel<<<NT, 256>>>(out, targets);
    loss_final_kernel<<<1, 256>>>(out, out_size);
}

// round 8
// speedup vs baseline: 6.0409x; 1.2991x over previous
#include <cuda_runtime.h>
#include <cuda_fp16.h>
#include <math.h>
#include <stdint.h>

#define NT    2048      // B*T
#define CDIM  384
#define TDIM  32
#define NHEAD 6
#define HEADD 64
#define VOCABSZ 50257
#define TILE_M 128
#define TILE_N 128
#define NMB   16        // NT/128
#define NNB   393       // ceil(VOCAB/128)
#define NCB   786       // stats blocks of 64 cols (2 per CTA N-tile)
#define KCH   32
#define NCHUNK 12       // 384/32
#define CHUNK_U 2048    // u32 (f16x2) per permuted 128x32 chunk
#define NSTAGE 4
#define STAGE_BYTES 16384
#define QKV_MAT_U (3 * NCHUNK * CHUNK_U)   // u32 per permuted qkv matrix

// ---- scratch ----
__device__ float g_h[NT * CDIM];
__device__ float g_q[NT * CDIM];
__device__ float g_k[NT * CDIM];
__device__ float g_v[NT * CDIM];
__device__ float g_pmax[NT * NCB];
__device__ float g_psum[NT * NCB];
__device__ float g_rowloss[NT];
__device__ uint32_t g_aperm[NMB * NCHUNK * CHUNK_U];       // 1.5 MB
__device__ uint32_t g_blm[NNB * NCHUNK * CHUNK_U];         // 38.6 MB
__device__ uint32_t g_bqkv[2 * 3 * QKV_MAT_U];             // 1.7 MB

// =========================================================================
// helpers
// =========================================================================
__device__ __forceinline__ uint32_t smem_u32(const void* p) {
    uint32_t a;
    asm("{ .reg .u64 t; cvta.to.shared.u64 t, %1; cvt.u32.u64 %0, t; }" : "=r"(a) : "l"(p));
    return a;
}
__device__ __forceinline__ uint32_t packh2(float x, float y) {
    __half2 h = __floats2half2_rn(x, y);
    return *(uint32_t*)&h;
}
__device__ __forceinline__ void mma_f16(float c[4], const uint32_t a[4], const uint32_t b[2]) {
    asm volatile(
        "mma.sync.aligned.m16n8k16.row.col.f32.f16.f16.f32 "
        "{%0,%1,%2,%3}, {%4,%5,%6,%7}, {%8,%9}, {%0,%1,%2,%3};"
        : "+f"(c[0]), "+f"(c[1]), "+f"(c[2]), "+f"(c[3])
        : "r"(a[0]), "r"(a[1]), "r"(a[2]), "r"(a[3]), "r"(b[0]), "r"(b[1]));
}
#define LDS128(r, addr) \
    asm volatile("ld.shared.v4.b32 {%0,%1,%2,%3}, [%4];" \
        : "=r"((r)[0]), "=r"((r)[1]), "=r"((r)[2]), "=r"((r)[3]) : "r"(addr))
#define LDS64(r, addr) \
    asm volatile("ld.shared.v2.b32 {%0,%1}, [%2];" \
        : "=r"((r)[0]), "=r"((r)[1]) : "r"(addr))
#define CP_ASYNC16(dst, src) \
    asm volatile("cp.async.cg.shared.global [%0], [%1], 16;" :: "r"(dst), "l"(src) : "memory")
#define CP_COMMIT() asm volatile("cp.async.commit_group;" ::: "memory")
#define CP_WAIT2()  asm volatile("cp.async.wait_group 2;" ::: "memory")

// SMEM: bias[128] @0 ; 4 stages of (A 8KB + B 8KB) @1024 ; epilogue stage reuses
#define SM_STAGE0 1024
#define SM_TOTAL  (1024 + 128 * 132 * 4)   // 68608 (epilogue dominates: 4*16K=64K < 67.6K)

// fp16 fragment-permuted layouts within a 128x32 chunk (m16n8k16):
//  A elem-pair (m, k0 even): s=k0>>4, mb=m>>4, lane=(m&7)*4+((k0>>1)&3),
//    reg=((m>>3)&1)+2*((k0>>3)&1);  u32 idx = ((s*8+mb)*32+lane)*4+reg
//  B elem-pair (n, k0 even): s=k0>>4, nb=n>>3, lane=(n&7)*4+((k0>>1)&3),
//    reg=(k0>>3)&1;                 u32 idx = ((s*16+nb)*32+lane)*2+reg

__device__ __forceinline__ void compute_chunk(uint32_t Abuf, uint32_t Bbuf,
                                              int wm, int wn, int lid,
                                              float c[2][8][4]) {
#pragma unroll
    for (int ks = 0; ks < 2; ks++) {
        uint32_t a[2][4];
#pragma unroll
        for (int r = 0; r < 2; r++)
            LDS128(a[r], Abuf + ((ks * 8 + wm * 2 + r) * 32 + lid) * 16);
        uint32_t b[8][2];
#pragma unroll
        for (int nf = 0; nf < 8; nf++)
            LDS64(b[nf], Bbuf + ((ks * 16 + wn * 8 + nf) * 32 + lid) * 8);
#pragma unroll
        for (int r = 0; r < 2; r++)
#pragma unroll
            for (int nf = 0; nf < 8; nf++)
                mma_f16(c[r][nf], a[r], b[nf]);
    }
}

__device__ __forceinline__ void supd(float& m, float& s, float v) {
    if (v > m) { s = s * __expf(m - v) + 1.f; m = v; }
    else       { s += __expf(v - m); }
}

// =========================================================================
// Permutation kernels (global fp32 -> fp16 fragment-permuted global)
// =========================================================================
__global__ void aperm_kernel(const float* __restrict__ A) {
    __shared__ uint32_t sbuf[CHUNK_U];
    const int tid = threadIdx.x;
    const int mb = blockIdx.x, kc = blockIdx.y;
    const int rb = tid >> 3, j = tid & 7;
    const float* Ag = A + (size_t)(mb * 128) * CDIM + kc * KCH + j * 4;
#pragma unroll
    for (int i = 0; i < 4; i++) {
        int r = i * 32 + rb;
        float4 v = *(const float4*)(Ag + (size_t)r * CDIM);
#pragma unroll
        for (int p = 0; p < 2; p++) {
            int k0 = j * 4 + 2 * p;
            int s = k0 >> 4;
            int lane = (r & 7) * 4 + ((k0 >> 1) & 3);
            int reg = ((r >> 3) & 1) + 2 * ((k0 >> 3) & 1);
            int idx = ((s * 8 + (r >> 4)) * 32 + lane) * 4 + reg;
            sbuf[idx] = packh2(p ? v.z : v.x, p ? v.w : v.y);
        }
    }
    __syncthreads();
    uint32_t* out = g_aperm + ((size_t)mb * NCHUNK + kc) * CHUNK_U;
#pragma unroll
    for (int i = 0; i < 2; i++)
        *(uint4*)(out + i * 1024 + tid * 4) = *(const uint4*)&sbuf[i * 1024 + tid * 4];
}

__global__ void bperm_kernel(const float* __restrict__ B0, const float* __restrict__ B1,
                             const float* __restrict__ B2,
                             uint32_t* __restrict__ O0, uint32_t* __restrict__ O1,
                             uint32_t* __restrict__ O2, int Ntot) {
    __shared__ uint32_t sbuf[CHUNK_U];
    const int tid = threadIdx.x;
    const int nb = blockIdx.x, kc = blockIdx.y, z = blockIdx.z;
    const float* B = (z == 0) ? B0 : (z == 1 ? B1 : B2);
    uint32_t* O = (z == 0) ? O0 : (z == 1 ? O1 : O2);
    const int rb = tid >> 3, j = tid & 7;
#pragma unroll
    for (int i = 0; i < 4; i++) {
        int r = i * 32 + rb;
        int n = nb * 128 + r;
        float4 v = (n < Ntot) ? *(const float4*)(B + (size_t)n * CDIM + kc * KCH + j * 4)
                              : make_float4(0.f, 0.f, 0.f, 0.f);
#pragma unroll
        for (int p = 0; p < 2; p++) {
            int k0 = j * 4 + 2 * p;
            int s = k0 >> 4;
            int lane = (r & 7) * 4 + ((k0 >> 1) & 3);
            int reg = (k0 >> 3) & 1;
            int idx = ((s * 16 + (r >> 3)) * 32 + lane) * 2 + reg;
            sbuf[idx] = packh2(p ? v.z : v.x, p ? v.w : v.y);
        }
    }
    __syncthreads();
    uint32_t* out = O + ((size_t)nb * NCHUNK + kc) * CHUNK_U;
#pragma unroll
    for (int i = 0; i < 2; i++)
        *(uint4*)(out + i * 1024 + tid * 4) = *(const uint4*)&sbuf[i * 1024 + tid * 4];
}

// =========================================================================
// fp16 tensor GEMM over pre-permuted operands.
// grid: (NMB, Nblocks, nz); z selects B/C pair (fused QKV). A = g_aperm.
// =========================================================================
template <bool STATS>
__global__ __launch_bounds__(256)
void mma_gemm(const uint32_t* __restrict__ Bp0, const uint32_t* __restrict__ Bp1,
              const uint32_t* __restrict__ Bp2,
              float* __restrict__ C0, float* __restrict__ C1, float* __restrict__ C2,
              const float* __restrict__ bias, int Ntot) {
    extern __shared__ __align__(1024) char smem[];
    const int tid = threadIdx.x;
    const int lid = tid & 31, wid = tid >> 5;
    const int wm = wid >> 1, wn = wid & 1;
    const int bm = blockIdx.x * TILE_M;
    const int bn = blockIdx.y * TILE_N;
    const uint32_t* Bperm = (blockIdx.z == 0) ? Bp0 : (blockIdx.z == 1 ? Bp1 : Bp2);
    float* C = (blockIdx.z == 0) ? C0 : (blockIdx.z == 1 ? C1 : C2);

    const uint32_t* Ac = g_aperm + (size_t)blockIdx.x * NCHUNK * CHUNK_U;
    const uint32_t* Bc = Bperm + (size_t)blockIdx.y * NCHUNK * CHUNK_U;

    float* biasS = (float*)smem;
    float* stage = (float*)(smem + SM_STAGE0);
    const uint32_t sb = smem_u32(smem);

    if (tid < TILE_N) {
        int n = bn + tid;
        biasS[tid] = (bias != nullptr && n < Ntot) ? bias[n] : 0.f;
    }

    float c[2][8][4];
#pragma unroll
    for (int r = 0; r < 2; r++)
#pragma unroll
        for (int nf = 0; nf < 8; nf++)
#pragma unroll
            for (int e = 0; e < 4; e++) c[r][nf][e] = 0.f;

    // ---- cp.async copy of one 16KB chunk (A 8K + B 8K) into stage s ----
    auto issue = [&](int kcc, int s) {
        uint32_t dA = sb + SM_STAGE0 + s * STAGE_BYTES + tid * 16;
        uint32_t dB = dA + 8192;
        const uint32_t* srcA = Ac + (size_t)kcc * CHUNK_U + tid * 4;
        const uint32_t* srcB = Bc + (size_t)kcc * CHUNK_U + tid * 4;
#pragma unroll
        for (int i = 0; i < 2; i++) {
            CP_ASYNC16(dA + i * 4096, srcA + i * 1024);
            CP_ASYNC16(dB + i * 4096, srcB + i * 1024);
        }
    };

    issue(0, 0); CP_COMMIT();
    issue(1, 1); CP_COMMIT();
    issue(2, 2); CP_COMMIT();

    for (int kc = 0; kc < NCHUNK; kc++) {
        CP_WAIT2();
        __syncthreads();                 // chunk kc visible; buf (kc-1)%4 free
        if (kc + 3 < NCHUNK) issue(kc + 3, (kc + 3) & 3);
        CP_COMMIT();
        const uint32_t base = sb + SM_STAGE0 + (kc & 3) * STAGE_BYTES;
        compute_chunk(base, base + 8192, wm, wn, lid, c);
    }
    __syncthreads();                     // all compute done before stage reuse

    // ---- epilogue: bias, stats, staged coalesced store ----
    float rm[2][2], rs[2][2];
#pragma unroll
    for (int r = 0; r < 2; r++)
#pragma unroll
        for (int h = 0; h < 2; h++) { rm[r][h] = -INFINITY; rs[r][h] = 0.f; }

    const int g = lid >> 2, t4 = lid & 3;
#pragma unroll
    for (int r = 0; r < 2; r++) {
        const int row = wm * 32 + r * 16 + g;
#pragma unroll
        for (int nf = 0; nf < 8; nf++) {
            const int col = wn * 64 + nf * 8 + t4 * 2;
            const float b0 = biasS[col], b1 = biasS[col + 1];
            float v0 = c[r][nf][0] + b0, v1 = c[r][nf][1] + b1;
            float v2 = c[r][nf][2] + b0, v3 = c[r][nf][3] + b1;
            *(float2*)&stage[row * 132 + col]       = make_float2(v0, v1);
            *(float2*)&stage[(row + 8) * 132 + col] = make_float2(v2, v3);
            if (STATS) {
                int n = bn + col;
                if (n < Ntot)     { supd(rm[r][0], rs[r][0], v0); supd(rm[r][1], rs[r][1], v2); }
                if (n + 1 < Ntot) { supd(rm[r][0], rs[r][0], v1); supd(rm[r][1], rs[r][1], v3); }
            }
        }
    }

    if (STATS) {
#pragma unroll
        for (int r = 0; r < 2; r++)
#pragma unroll
            for (int h = 0; h < 2; h++) {
                float m = rm[r][h], s = rs[r][h];
#pragma unroll
                for (int off = 1; off <= 2; off <<= 1) {
                    float om = __shfl_xor_sync(0xffffffffu, m, off);
                    float os = __shfl_xor_sync(0xffffffffu, s, off);
                    float M = fmaxf(m, om);
                    float S = ((m > -INFINITY) ? s * __expf(m - M) : 0.f) +
                              ((om > -INFINITY) ? os * __expf(om - M) : 0.f);
                    m = M; s = S;
                }
                if (t4 == 0) {
                    int mrow = bm + wm * 32 + r * 16 + h * 8 + g;
                    size_t idx = (size_t)mrow * NCB + blockIdx.y * 2 + wn;
                    g_pmax[idx] = m;
                    g_psum[idx] = s;
                }
            }
    }

    __syncthreads();
#pragma unroll 8
    for (int it = 0; it < 64; it++) {
        int idx = it * 256 + tid;
        int rr = idx >> 7, cc = idx & 127;
        int n = bn + cc;
        if (n < Ntot) C[(size_t)(bm + rr) * Ntot + n] = stage[rr * 132 + cc];
    }
}

// =========================================================================
// Embedding
// =========================================================================
__global__ void embed_kernel(const int* __restrict__ x,
                             const float* __restrict__ w_e,
                             const float* __restrict__ pos) {
    int idx = blockIdx.x * blockDim.x + threadIdx.x;
    if (idx >= NT * CDIM) return;
    int bt = idx / CDIM, c = idx % CDIM;
    int tok = x[bt];
    g_h[idx] = w_e[(size_t)tok * CDIM + c] + pos[(bt % TDIM) * CDIM + c];
}

// =========================================================================
// Attention (T=32, D=64, causal, h += attn)
// =========================================================================
__global__ void attn_kernel() {
    __shared__ float qs[32][65];
    __shared__ float ks[32][65];
    __shared__ float vs[32][65];
    __shared__ float w[32][33];

    const int bh = blockIdx.x;
    const int b = bh / NHEAD, hd = bh % NHEAD;
    const int tid = threadIdx.x;
    const int base = (b * TDIM) * CDIM + hd * HEADD;

    for (int i = tid; i < 32 * 64; i += 256) {
        int t = i >> 6, d = i & 63;
        int g = base + t * CDIM + d;
        qs[t][d] = g_q[g];
        ks[t][d] = g_k[g];
        vs[t][d] = g_v[g];
    }
    __syncthreads();

    const float scale = 0.125f;
    for (int i = tid; i < 32 * 32; i += 256) {
        int t = i >> 5, s = i & 31;
        float v = -INFINITY;
        if (s <= t) {
            float acc = 0.f;
#pragma unroll
            for (int d = 0; d < 64; d++) acc += qs[t][d] * ks[s][d];
            v = acc * scale;
        }
        w[t][s] = v;
    }
    __syncthreads();

    if (tid < 32) {
        int t = tid;
        float mx = -INFINITY;
        for (int s = 0; s <= t; s++) mx = fmaxf(mx, w[t][s]);
        float sum = 0.f;
        for (int s = 0; s <= t; s++) { float e = expf(w[t][s] - mx); w[t][s] = e; sum += e; }
        float inv = 1.f / sum;
        for (int s = 0; s <= t; s++) w[t][s] *= inv;
        for (int s = t + 1; s < 32; s++) w[t][s] = 0.f;
    }
    __syncthreads();

    for (int i = tid; i < 32 * 64; i += 256) {
        int t = i >> 6, d = i & 63;
        float acc = 0.f;
#pragma unroll
        for (int s = 0; s < 32; s++) acc += w[t][s] * vs[s][d];
        g_h[base + t * CDIM + d] += acc;
    }
}

// =========================================================================
// Loss
// =========================================================================
__global__ void loss_rows_kernel(const float* __restrict__ logits,
                                 const int* __restrict__ targets) {
    const int row = blockIdx.x;
    const int tid = threadIdx.x;
    float m = -INFINITY, s = 0.f;
    for (int cb = tid; cb < NCB; cb += 256) {
        float mi = g_pmax[(size_t)row * NCB + cb];
        float si = g_psum[(size_t)row * NCB + cb];
        if (mi > m) { s = s * expf(m - mi) + si; m = mi; }
        else if (mi > -INFINITY) { s += si * expf(mi - m); }
    }
    __shared__ float sm[256], ss[256];
    sm[tid] = m; ss[tid] = s;
    __syncthreads();
    for (int st = 128; st > 0; st >>= 1) {
        if (tid < st) {
            float m1 = sm[tid], s1 = ss[tid];
            float m2 = sm[tid + st], s2 = ss[tid + st];
            float M = fmaxf(m1, m2);
            float S = ((m1 > -INFINITY) ? s1 * expf(m1 - M) : 0.f) +
                      ((m2 > -INFINITY) ? s2 * expf(m2 - M) : 0.f);
            sm[tid] = M; ss[tid] = S;
        }
        __syncthreads();
    }
    if (tid == 0) {
        float logZ = sm[0] + logf(ss[0]);
        int t = targets[row];
        float lt = logits[(size_t)row * VOCABSZ + t];
        g_rowloss[row] = logZ - lt;
    }
}

__global__ void loss_final_kernel(float* __restrict__ out, int out_size) {
    __shared__ float sm[256];
    const int tid = threadIdx.x;
    float s = 0.f;
    for (int r = tid; r < NT; r += 256) s += g_rowloss[r];
    sm[tid] = s;
    __syncthreads();
    for (int st = 128; st > 0; st >>= 1) {
        if (tid < st) sm[tid] += sm[tid + st];
        __syncthreads();
    }
    if (tid == 0) {
        float loss = sm[0] / (float)NT;
        size_t logits_elems = (size_t)NT * VOCABSZ;
        if ((size_t)out_size > logits_elems) out[logits_elems] = loss;
    }
}

// =========================================================================
extern "C" void kernel_launch(void* const* d_in, const int* in_sizes, int n_in,
                              void* d_out, int out_size) {
    const int*   x       = (const int*)d_in[0];
    const int*   targets = (const int*)d_in[1];
    const float* w_e     = (const float*)d_in[2];
    const float* pos     = (const float*)d_in[3];
    const float* Wq      = (const float*)d_in[4];
    const float* Wk      = (const float*)d_in[5];
    const float* Wv      = (const float*)d_in[6];
    const float* lm_w    = (const float*)d_in[7];
    const float* lm_b    = (const float*)d_in[8];
    float* out = (float*)d_out;

    float *ph, *pq, *pk, *pv;
    uint32_t *pblm, *pbqkv;
    cudaGetSymbolAddress((void**)&ph, g_h);
    cudaGetSymbolAddress((void**)&pq, g_q);
    cudaGetSymbolAddress((void**)&pk, g_k);
    cudaGetSymbolAddress((void**)&pv, g_v);
    cudaGetSymbolAddress((void**)&pblm, g_blm);
    cudaGetSymbolAddress((void**)&pbqkv, g_bqkv);

    cudaFuncSetAttribute(mma_gemm<false>, cudaFuncAttributeMaxDynamicSharedMemorySize, SM_TOTAL);
    cudaFuncSetAttribute(mma_gemm<true>,  cudaFuncAttributeMaxDynamicSharedMemorySize, SM_TOTAL);

    embed_kernel<<<(NT * CDIM + 255) / 256, 256>>>(x, w_e, pos);

    const size_t wstride = (size_t)NHEAD * HEADD * CDIM;
    // permute all weights (lm_w + 2 layers of Q/K/V)
    bperm_kernel<<<dim3(NNB, NCHUNK, 1), 256>>>(lm_w, lm_w, lm_w, pblm, pblm, pblm, VOCABSZ);
    for (int l = 0; l < 2; l++) {
        uint32_t* bq = pbqkv + (size_t)(l * 3 + 0) * QKV_MAT_U;
        uint32_t* bk = pbqkv + (size_t)(l * 3 + 1) * QKV_MAT_U;
        uint32_t* bv = pbqkv + (size_t)(l * 3 + 2) * QKV_MAT_U;
        bperm_kernel<<<dim3(3, NCHUNK, 3), 256>>>(
            Wq + l * wstride, Wk + l * wstride, Wv + l * wstride, bq, bk, bv, CDIM);
    }

    for (int l = 0; l < 2; l++) {
        uint32_t* bq = pbqkv + (size_t)(l * 3 + 0) * QKV_MAT_U;
        uint32_t* bk = pbqkv + (size_t)(l * 3 + 1) * QKV_MAT_U;
        uint32_t* bv = pbqkv + (size_t)(l * 3 + 2) * QKV_MAT_U;
        aperm_kernel<<<dim3(NMB, NCHUNK), 256>>>(ph);
        mma_gemm<false><<<dim3(NMB, 3, 3), 256, SM_TOTAL>>>(
            bq, bk, bv, pq, pk, pv, nullptr, CDIM);
        attn_kernel<<<(NT / TDIM) * NHEAD, 256>>>();
    }

    aperm_kernel<<<dim3(NMB, NCHUNK), 256>>>(ph);
    mma_gemm<true><<<dim3(NMB, NNB, 1), 256, SM_TOTAL>>>(
        pblm, pblm, pblm, out, out, out, lm_b, VOCABSZ);

    loss_rows_kernel<<<NT, 256>>>(out, targets);
    loss_final_kernel<<<1, 256>>>(out, out_size);
}